// round 2
// baseline (speedup 1.0000x reference)
#include <cuda_runtime.h>
#include <math.h>
#include <stdint.h>

#define NCB   8
#define MEMB  1024
#define DEMB  128
#define HLAT  64
#define BATCH 256
#define LPER  (BATCH*HLAT)              /* 16384 per codebook */
#define ZQ_ELEMS (BATCH*NCB*DEMB*HLAT)  /* 16777216 */
#define IDX_ELEMS (BATCH*NCB*HLAT)      /* 131072 */

// ---------------- device scratch (static, no allocations) ----------------
__device__ int   g_indices[NCB*LPER];     // argmin result per (n,l)
__device__ float g_esq[NCB*MEMB];         // ||e||^2 (sequential-order, bit-matching ref)
__device__ float g_xsq[NCB*LPER];         // ||x||^2 (sequential-order, bit-matching ref)
__device__ float g_part[2048];            // per-block loss partial sums
__device__ float g_ent[NCB];              // per-codebook entropy

// ---------------- e_sq: sequential square->add, ascending d ----------------
__global__ void esq_kernel(const float* __restrict__ emb) {
    int t = blockIdx.x * blockDim.x + threadIdx.x;   // 0..8191 -> (n,m)
    if (t >= NCB*MEMB) return;
    const float* row = emb + (size_t)t * DEMB;
    float acc = 0.f;
    #pragma unroll 8
    for (int d = 0; d < DEMB; d++) {
        float v  = row[d];
        float sq = __fmul_rn(v, v);        // rounded square (separate op, no FMA)
        acc = __fadd_rn(acc, sq);          // strict sequential order
    }
    g_esq[t] = acc;
}

// ---------------- x_sq: sequential square->add, ascending d ----------------
// Block per (n,b): stage x tile [d=128][h=64] coalesced into smem, then 64
// threads each reduce one row h sequentially over d (exact reference order).
__global__ void __launch_bounds__(256)
xsq_kernel(const float* __restrict__ x) {
    __shared__ float tile[8192];           // [d*64 + h]
    const int blk = blockIdx.x;
    const int n = blk & 7;
    const int b = blk >> 3;
    const int tid = threadIdx.x;
    const size_t base = (size_t)b*65536 + (size_t)n*8192;
    for (int i = tid; i < 8192; i += 256) tile[i] = x[base + i];
    __syncthreads();
    if (tid < 64) {
        const int h = tid;
        float acc = 0.f;
        #pragma unroll 8
        for (int d = 0; d < DEMB; d++) {
            float v  = tile[d*64 + h];
            float sq = __fmul_rn(v, v);
            acc = __fadd_rn(acc, sq);
        }
        g_xsq[n*LPER + b*HLAT + h] = acc;
    }
}

// ---------------- argmin distance GEMM ----------------
// Per block: codebook n, 128 l-rows, loop 8 chunks of 128 codes.
// Xs: [k=128][l=128] (transposed X tile), Es: [k=128][m=128] padded to 132.
// 256 threads = 16(ty,l) x 16(tx,m), each computes 8x8 micro-tile.
// Dot product: single-accumulator fmaf chain, ascending k (matches f32 gemm).
__global__ void __launch_bounds__(256, 1)
argmin_kernel(const float* __restrict__ x, const float* __restrict__ emb) {
    extern __shared__ float sm[];
    float* Xs = sm;               // 128*128
    float* Es = sm + 128*128;     // 128*132

    const int n    = blockIdx.x >> 7;
    const int tile = blockIdx.x & 127;
    const int l0   = tile * 128;
    const int tid  = threadIdx.x;
    const int tx   = tid & 15;
    const int ty   = tid >> 4;
    const int b0   = l0 / HLAT;   // = tile*2

    // Load X tile transposed: Xs[d][j], j = bb*64 + h
    for (int idx = tid; idx < 128*128; idx += 256) {
        int d  = idx >> 7;
        int j  = idx & 127;
        int bb = j >> 6;
        int h  = j & 63;
        Xs[d*128 + j] = x[(size_t)(b0 + bb)*65536 + (size_t)n*8192 + d*64 + h];
    }

    // per-row x_sq (constant over m, but needed for ref-identical rounding)
    float xr[8];
    #pragma unroll
    for (int i = 0; i < 8; i++) xr[i] = g_xsq[n*LPER + l0 + ty*8 + i];

    float bestd[8];
    int   bestm[8];
    #pragma unroll
    for (int i = 0; i < 8; i++) { bestd[i] = 3.4e38f; bestm[i] = 0; }

    for (int mc = 0; mc < 8; mc++) {
        __syncthreads();
        // Load E chunk transposed: Es[d][r] = emb[n, mc*128+r, d]
        for (int idx = tid; idx < 128*128; idx += 256) {
            int r = idx >> 7;
            int d = idx & 127;
            Es[d*132 + r] = emb[(size_t)n*(MEMB*DEMB) + (size_t)(mc*128 + r)*DEMB + d];
        }
        __syncthreads();

        float acc[8][8];
        #pragma unroll
        for (int i = 0; i < 8; i++)
            #pragma unroll
            for (int j = 0; j < 8; j++) acc[i][j] = 0.f;

        #pragma unroll 4
        for (int k = 0; k < 128; k++) {   // ascending k, single accumulator
            float4 a0 = *(const float4*)(Xs + k*128 + ty*8);
            float4 a1 = *(const float4*)(Xs + k*128 + ty*8 + 4);
            float4 c0 = *(const float4*)(Es + k*132 + tx*8);
            float4 c1 = *(const float4*)(Es + k*132 + tx*8 + 4);
            float a[8] = {a0.x,a0.y,a0.z,a0.w,a1.x,a1.y,a1.z,a1.w};
            float b[8] = {c0.x,c0.y,c0.z,c0.w,c1.x,c1.y,c1.z,c1.w};
            #pragma unroll
            for (int i = 0; i < 8; i++)
                #pragma unroll
                for (int j = 0; j < 8; j++)
                    acc[i][j] = fmaf(a[i], b[j], acc[i][j]);
        }

        // epilogue: d = round(round(e_sq + x_sq) - 2*dot)   [exact ref rounding]
        #pragma unroll
        for (int j = 0; j < 8; j++) {
            int m = mc*128 + tx*8 + j;
            float esq = g_esq[n*MEMB + m];
            #pragma unroll
            for (int i = 0; i < 8; i++) {
                float s  = __fadd_rn(esq, xr[i]);           // rounded at ~128
                float dd = __fsub_rn(s, 2.0f*acc[i][j]);    // 2*acc exact
                if (dd < bestd[i]) { bestd[i] = dd; bestm[i] = m; } // first-min tie-break
            }
        }
    }

    // Reduce across tx (16 lanes share the same 8 l-rows); prefer lowest m on ties
    #pragma unroll
    for (int i = 0; i < 8; i++) {
        float bd = bestd[i];
        int   bm = bestm[i];
        #pragma unroll
        for (int off = 8; off; off >>= 1) {
            float od = __shfl_xor_sync(0xffffffffu, bd, off);
            int   om = __shfl_xor_sync(0xffffffffu, bm, off);
            if (od < bd || (od == bd && om < bm)) { bd = od; bm = om; }
        }
        if (tx == 0) g_indices[n*LPER + l0 + ty*8 + i] = bm;
    }
}

// ---------------- gather + z_q + loss partials + indices out ----------------
__global__ void __launch_bounds__(256)
gather_kernel(const float* __restrict__ x, const float* __restrict__ emb,
              float* __restrict__ out, float* __restrict__ out_idx, int write_extras) {
    __shared__ int   midx[64];
    __shared__ float rows[64*129];
    __shared__ float red[256];

    const int blk = blockIdx.x;
    const int n = blk & 7;
    const int b = blk >> 3;
    const int tid = threadIdx.x;

    if (tid < 64) {
        int m = g_indices[n*LPER + b*HLAT + tid];
        midx[tid] = m;
        if (write_extras) out_idx[b*(NCB*HLAT) + n*HLAT + tid] = (float)m;
    }
    __syncthreads();

    for (int idx = tid; idx < 64*128; idx += 256) {
        int r = idx >> 7;
        int d = idx & 127;
        rows[r*129 + d] = emb[(size_t)n*(MEMB*DEMB) + (size_t)midx[r]*DEMB + d];
    }
    __syncthreads();

    float s = 0.f;
    const size_t base = (size_t)b*65536 + (size_t)n*8192;
    for (int idx = tid; idx < 8192; idx += 256) {   // idx = d*64 + h
        int d = idx >> 6;
        int h = idx & 63;
        float q  = rows[h*129 + d];
        float xv = x[base + idx];
        out[base + idx] = q;                          // z_q == quantized (STE adds exact 0)
        float df = xv - q;
        s += df*df;
    }

    red[tid] = s;
    __syncthreads();
    for (int st = 128; st; st >>= 1) {
        if (tid < st) red[tid] += red[tid + st];
        __syncthreads();
    }
    if (tid == 0) g_part[blk] = red[0];
}

// ---------------- per-codebook entropy ----------------
__global__ void entropy_kernel() {
    __shared__ int   hist[MEMB];
    __shared__ float red[256];
    const int n = blockIdx.x;
    const int tid = threadIdx.x;

    for (int i = tid; i < MEMB; i += 256) hist[i] = 0;
    __syncthreads();
    for (int l = tid; l < LPER; l += 256)
        atomicAdd(&hist[g_indices[n*LPER + l]], 1);
    __syncthreads();

    float s = 0.f;
    for (int m = tid; m < MEMB; m += 256) {
        float p = (float)hist[m] * (1.f / (float)LPER);
        s += p * logf(p + 1e-10f);
    }
    red[tid] = s;
    __syncthreads();
    for (int st = 128; st; st >>= 1) {
        if (tid < st) red[tid] += red[tid + st];
        __syncthreads();
    }
    if (tid == 0) g_ent[n] = -red[0];
}

// ---------------- finalize scalars ----------------
__global__ void finalize_kernel(float* __restrict__ out, int write_scalars) {
    __shared__ float red[256];
    const int tid = threadIdx.x;
    float s = 0.f;
    for (int i = tid; i < 2048; i += 256) s += g_part[i];   // fixed order: deterministic
    red[tid] = s;
    __syncthreads();
    for (int st = 128; st; st >>= 1) {
        if (tid < st) red[tid] += red[tid + st];
        __syncthreads();
    }
    if (tid == 0 && write_scalars) {
        float loss = 0.25f * red[0] / (float)ZQ_ELEMS;
        float ent = 0.f, perp = 0.f;
        #pragma unroll
        for (int n = 0; n < NCB; n++) { ent += g_ent[n]; perp += expf(g_ent[n]); }
        out[ZQ_ELEMS + 0] = loss;
        out[ZQ_ELEMS + 1] = ent * (1.f / NCB);
        out[ZQ_ELEMS + 2] = perp * (1.f / NCB);
    }
}

// ---------------- launch ----------------
extern "C" void kernel_launch(void* const* d_in, const int* in_sizes, int n_in,
                              void* d_out, int out_size) {
    const float* x   = (const float*)d_in[0];
    const float* emb = (const float*)d_in[1];
    if (n_in >= 2 && in_sizes[0] == NCB*MEMB*DEMB && in_sizes[1] == ZQ_ELEMS) {
        const float* t = x; x = emb; emb = t;   // defensive input-order swap
    }
    float* out = (float*)d_out;
    const int full = (out_size >= ZQ_ELEMS + 3 + IDX_ELEMS) ? 1 : 0;

    cudaFuncSetAttribute(argmin_kernel,
                         cudaFuncAttributeMaxDynamicSharedMemorySize, 133120);

    esq_kernel<<<(NCB*MEMB + 255)/256, 256>>>(emb);
    xsq_kernel<<<BATCH * NCB, 256>>>(x);
    argmin_kernel<<<NCB * (LPER/128), 256, 133120>>>(x, emb);
    gather_kernel<<<BATCH * NCB, 256>>>(x, emb, out, out + ZQ_ELEMS + 3, full);
    entropy_kernel<<<NCB, 256>>>();
    finalize_kernel<<<1, 256>>>(out, full);
}

// round 4
// speedup vs baseline: 1.1303x; 1.1303x over previous
#include <cuda_runtime.h>
#include <cuda_bf16.h>
#include <math.h>
#include <stdint.h>

#define NCB   8
#define MEMB  1024
#define DEMB  128
#define HLAT  64
#define BATCH 256
#define LPER  (BATCH*HLAT)              /* 16384 per codebook */
#define ZQ_ELEMS (BATCH*NCB*DEMB*HLAT)  /* 16777216 */
#define IDX_ELEMS (BATCH*NCB*HLAT)      /* 131072 */
#define MARGIN 4e-4f

// ---------------- device scratch ----------------
__device__ int   g_indices[NCB*LPER];
__device__ float g_esq[NCB*MEMB];
__device__ float g_xsq[NCB*LPER];
__device__ float g_part[2048];
__device__ float g_ent[NCB];
__device__ int   g_ucount;
__device__ int   g_ulist[NCB*LPER];
// pre-swizzled bf16 embedding tiles: [n][mchunk 8][row 128][k 128], 16B-chunk XOR swizzle
__device__ __nv_bfloat16 g_bhi[NCB*MEMB*DEMB];
__device__ __nv_bfloat16 g_blo[NCB*MEMB*DEMB];

// ---------------- PTX helpers ----------------
__device__ __forceinline__ uint32_t smem_u32(const void* p) {
    uint32_t a;
    asm("{ .reg .u64 t; cvta.to.shared.u64 t, %1; cvt.u32.u64 %0, t; }" : "=r"(a) : "l"(p));
    return a;
}
__device__ __forceinline__ void ldsm4(uint32_t* r, uint32_t addr) {
    asm volatile("ldmatrix.sync.aligned.m8n8.x4.shared.b16 {%0,%1,%2,%3}, [%4];"
        : "=r"(r[0]), "=r"(r[1]), "=r"(r[2]), "=r"(r[3]) : "r"(addr));
}
__device__ __forceinline__ void mma_bf16(float* c, const uint32_t* a, const uint32_t* b) {
    asm volatile("mma.sync.aligned.m16n8k16.row.col.f32.bf16.bf16.f32 "
        "{%0,%1,%2,%3}, {%4,%5,%6,%7}, {%8,%9}, {%0,%1,%2,%3};"
        : "+f"(c[0]), "+f"(c[1]), "+f"(c[2]), "+f"(c[3])
        : "r"(a[0]), "r"(a[1]), "r"(a[2]), "r"(a[3]), "r"(b[0]), "r"(b[1]));
}

// ---------------- e_sq (exact sequential) + ucount reset ----------------
__global__ void esq_kernel(const float* __restrict__ emb) {
    int t = blockIdx.x * blockDim.x + threadIdx.x;
    if (t == 0) g_ucount = 0;
    if (t >= NCB*MEMB) return;
    const float* row = emb + (size_t)t * DEMB;
    float acc = 0.f;
    #pragma unroll 8
    for (int d = 0; d < DEMB; d++) {
        float v = row[d];
        acc = __fadd_rn(acc, __fmul_rn(v, v));
    }
    g_esq[t] = acc;
}

// ---------------- x_sq (exact sequential) ----------------
__global__ void __launch_bounds__(256)
xsq_kernel(const float* __restrict__ x) {
    __shared__ float tile[8192];
    const int n = blockIdx.x & 7, b = blockIdx.x >> 3, tid = threadIdx.x;
    const size_t base = (size_t)b*65536 + (size_t)n*8192;
    for (int i = tid; i < 8192; i += 256) tile[i] = x[base + i];
    __syncthreads();
    if (tid < 64) {
        float acc = 0.f;
        #pragma unroll 8
        for (int d = 0; d < DEMB; d++) {
            float v = tile[d*64 + tid];
            acc = __fadd_rn(acc, __fmul_rn(v, v));
        }
        g_xsq[n*LPER + b*HLAT + tid] = acc;
    }
}

// ---------------- embedding -> swizzled bf16 hi/lo tiles ----------------
// elem = ((n*8+mc)*128 + row)*128 + ((chunk16 ^ (row&7))<<3) + (d&7)
__global__ void bprep_kernel(const float* __restrict__ emb) {
    int u = blockIdx.x * blockDim.x + threadIdx.x;
    if (u >= NCB*MEMB*DEMB) return;
    float v = emb[u];
    int d = u & 127, m = (u >> 7) & 1023, n = u >> 17;
    __nv_bfloat16 h = __float2bfloat16(v);
    __nv_bfloat16 l = __float2bfloat16(v - __bfloat162float(h));
    int row = m & 127, mc = m >> 7;
    int elem = ((n*8 + mc)*128 + row)*128 + (((d >> 3) ^ (row & 7)) << 3) + (d & 7);
    g_bhi[elem] = h;
    g_blo[elem] = l;
}

// ---------------- pass 1: tensor-core (mma.sync) approximate argmin ----------------
// CTA = (n, l-tile of 128). A[l=128,k=128] bf16 hi/lo (swizzled) in smem,
// loop 8 chunks of 128 codes; C = A.B^T f32, 3 combos (hh+hl+lh) fused into
// the same accumulator. Track best/second/idx per row in regs.
__global__ void __launch_bounds__(256, 1)
argmin_mma(const float* __restrict__ x) {
    extern __shared__ char smraw[];
    uint32_t sraw = smem_u32(smraw);
    uint32_t sb = (sraw + 1023u) & ~1023u;
    char* sm = smraw + (sb - sraw);
    __nv_bfloat16* Ahi = (__nv_bfloat16*)(sm);            // 32KB
    __nv_bfloat16* Alo = (__nv_bfloat16*)(sm + 32768);    // 32KB
    __nv_bfloat16* Bhi = (__nv_bfloat16*)(sm + 65536);    // 32KB
    __nv_bfloat16* Blo = (__nv_bfloat16*)(sm + 98304);    // 32KB
    float* esq_s = (float*)(sm + 131072);                 // 4KB
    float* sbest = (float*)(sm + 135168);                 // 256 f32
    float* ssec  = (float*)(sm + 136192);                 // 256 f32
    int*   sidx  = (int*)  (sm + 137216);                 // 256 int

    const int n  = blockIdx.x >> 7;
    const int lt = blockIdx.x & 127;
    const int l0 = lt * 128;
    const int b0 = lt * 2;
    const int tid  = threadIdx.x;
    const int lane = tid & 31;
    const int w    = tid >> 5;
    const int wl   = w & 3;     // l quarter (32 rows)
    const int wm   = w >> 2;    // m half (64 cols)

    // stage e_sq
    for (int i = tid; i < 1024; i += 256) esq_s[i] = g_esq[n*1024 + i];

    // stage + split-convert A tile (swizzled)
    for (int idx = tid; idx < 16384; idx += 256) {
        int d = idx >> 7, j = idx & 127;
        float v = x[(size_t)(b0 + (j >> 6))*65536 + (size_t)n*8192 + d*64 + (j & 63)];
        __nv_bfloat16 h = __float2bfloat16(v);
        __nv_bfloat16 l = __float2bfloat16(v - __bfloat162float(h));
        int elem = j*128 + (((d >> 3) ^ (j & 7)) << 3) + (d & 7);
        Ahi[elem] = h; Alo[elem] = l;
    }

    // ldmatrix per-lane address precompute
    const uint32_t sAh = sb, sBh = sb + 65536;
    const int q  = lane >> 3;
    const int r8 = lane & 7;
    const int cqA = q >> 1;     // A: k-chunk select
    const int cqB = q & 1;      // B: k-chunk select
    uint32_t aBase[2]; int a7[2];
    #pragma unroll
    for (int t2 = 0; t2 < 2; t2++) {
        int rowA = wl*32 + t2*16 + r8 + (q & 1)*8;
        aBase[t2] = sAh + rowA*256; a7[t2] = rowA & 7;
    }
    uint32_t bBase[4]; int b7[4];
    #pragma unroll
    for (int p = 0; p < 4; p++) {
        int rowB = wm*64 + p*16 + r8 + (q >> 1)*8;
        bBase[p] = sBh + rowB*256; b7[p] = rowB & 7;
    }

    // per-row best/second tracking: 4 slots = (ltile 0/1) x (row g / g+8)
    float best[4], sec[4];
    int   idxm[4];
    #pragma unroll
    for (int s = 0; s < 4; s++) { best[s] = 3.4e38f; sec[s] = 3.4e38f; idxm[s] = 0; }

    const int col2 = (lane & 3) * 2;

    __syncthreads();

    for (int mc = 0; mc < 8; mc++) {
        // stage B chunk (pre-swizzled, pure memcpy)
        {
            const uint4* sh = (const uint4*)(g_bhi + ((size_t)(n*8 + mc) << 14));
            const uint4* sl = (const uint4*)(g_blo + ((size_t)(n*8 + mc) << 14));
            uint4* dh = (uint4*)Bhi; uint4* dl = (uint4*)Blo;
            #pragma unroll
            for (int i = 0; i < 8; i++) { dh[tid + i*256] = sh[tid + i*256]; dl[tid + i*256] = sl[tid + i*256]; }
        }
        __syncthreads();

        float acc[2][8][4];
        #pragma unroll
        for (int t2 = 0; t2 < 2; t2++)
            #pragma unroll
            for (int mt = 0; mt < 8; mt++)
                #pragma unroll
                for (int c = 0; c < 4; c++) acc[t2][mt][c] = 0.f;

        #pragma unroll
        for (int ks = 0; ks < 8; ks++) {
            const int ks2 = ks * 2;
            uint32_t ah[2][4], al[2][4];
            #pragma unroll
            for (int t2 = 0; t2 < 2; t2++) {
                uint32_t off = (uint32_t)(((ks2 + cqA) ^ a7[t2]) << 4);
                ldsm4(ah[t2], aBase[t2] + off);
                ldsm4(al[t2], aBase[t2] + off + 32768);
            }
            uint32_t bh[4][4], bl[4][4];
            #pragma unroll
            for (int p = 0; p < 4; p++) {
                uint32_t off = (uint32_t)(((ks2 + cqB) ^ b7[p]) << 4);
                ldsm4(bh[p], bBase[p] + off);
                ldsm4(bl[p], bBase[p] + off + 32768);
            }
            #pragma unroll
            for (int t2 = 0; t2 < 2; t2++)
                #pragma unroll
                for (int p = 0; p < 4; p++) {
                    mma_bf16(acc[t2][2*p],   ah[t2], &bh[p][0]);
                    mma_bf16(acc[t2][2*p+1], ah[t2], &bh[p][2]);
                    mma_bf16(acc[t2][2*p],   ah[t2], &bl[p][0]);
                    mma_bf16(acc[t2][2*p+1], ah[t2], &bl[p][2]);
                    mma_bf16(acc[t2][2*p],   al[t2], &bh[p][0]);
                    mma_bf16(acc[t2][2*p+1], al[t2], &bh[p][2]);
                }
        }

        // epilogue: t = e_sq - 2*dot ; update best/second (m ascending per slot)
        const int mbase = mc*128 + wm*64;
        #pragma unroll
        for (int t2 = 0; t2 < 2; t2++) {
            #pragma unroll
            for (int mt = 0; mt < 8; mt++) {
                float e0 = esq_s[mbase + mt*8 + col2];
                float e1 = esq_s[mbase + mt*8 + col2 + 1];
                int m0 = mbase + mt*8 + col2;
                // slot s0 = row g
                {
                    int s = t2*2;
                    float ta = e0 - 2.f*acc[t2][mt][0];
                    float tb = e1 - 2.f*acc[t2][mt][1];
                    if (ta < best[s]) { sec[s] = best[s]; best[s] = ta; idxm[s] = m0; }
                    else if (ta < sec[s]) sec[s] = ta;
                    if (tb < best[s]) { sec[s] = best[s]; best[s] = tb; idxm[s] = m0 + 1; }
                    else if (tb < sec[s]) sec[s] = tb;
                }
                // slot s1 = row g+8
                {
                    int s = t2*2 + 1;
                    float ta = e0 - 2.f*acc[t2][mt][2];
                    float tb = e1 - 2.f*acc[t2][mt][3];
                    if (ta < best[s]) { sec[s] = best[s]; best[s] = ta; idxm[s] = m0; }
                    else if (ta < sec[s]) sec[s] = ta;
                    if (tb < best[s]) { sec[s] = best[s]; best[s] = tb; idxm[s] = m0 + 1; }
                    else if (tb < sec[s]) sec[s] = tb;
                }
            }
        }
        __syncthreads();   // all warps done reading B before restage
    }

    // quad reduce (lanes sharing lane>>2 hold the same rows)
    #pragma unroll
    for (int s = 0; s < 4; s++) {
        float b = best[s], sc = sec[s];
        int   im = idxm[s];
        #pragma unroll
        for (int off = 1; off <= 2; off <<= 1) {
            float ob = __shfl_xor_sync(0xffffffffu, b,  off);
            float os = __shfl_xor_sync(0xffffffffu, sc, off);
            int   oi = __shfl_xor_sync(0xffffffffu, im, off);
            if (ob < b || (ob == b && oi < im)) {
                sc = fminf(b, os); b = ob; im = oi;
            } else {
                sc = fminf(sc, ob);
            }
        }
        best[s] = b; sec[s] = sc; idxm[s] = im;
    }
    if ((lane & 3) == 0) {
        const int g = lane >> 2;
        #pragma unroll
        for (int s = 0; s < 4; s++) {
            int row = wl*32 + (s >> 1)*16 + g + (s & 1)*8;
            sbest[wm*128 + row] = best[s];
            ssec [wm*128 + row] = sec[s];
            sidx [wm*128 + row] = idxm[s];
        }
    }
    __syncthreads();

    if (tid < 128) {
        float b0f = sbest[tid],        b1f = sbest[128 + tid];
        float s0f = ssec[tid],         s1f = ssec[128 + tid];
        int   i0  = sidx[tid],         i1  = sidx[128 + tid];
        float b, s; int im;
        if (b1f < b0f || (b1f == b0f && i1 < i0)) { b = b1f; im = i1; s = fminf(b0f, s1f); }
        else { b = b0f; im = i0; s = fminf(s0f, b1f); }
        int l = l0 + tid;
        g_indices[n*LPER + l] = im;
        if (s - b < MARGIN) {
            int p = atomicAdd(&g_ucount, 1);
            g_ulist[p] = (n << 14) | l;
        }
    }
}

// ---------------- pass 2: exact rescan of uncertain rows ----------------
__global__ void __launch_bounds__(256)
fixup_kernel(const float* __restrict__ x, const float* __restrict__ emb) {
    __shared__ float xs[128];
    __shared__ float sD[256];
    __shared__ int   sM[256];
    const int tid = threadIdx.x;
    const int cnt = g_ucount;
    for (int u = blockIdx.x; u < cnt; u += gridDim.x) {
        int id = g_ulist[u];
        int n = id >> 14, l = id & 16383;
        int b = l >> 6, h = l & 63;
        __syncthreads();
        if (tid < 128) xs[tid] = x[(size_t)b*65536 + (size_t)n*8192 + tid*64 + h];
        __syncthreads();
        float xsq = g_xsq[n*LPER + l];
        float bD = 3.4e38f; int bM = 0;
        for (int mm = 0; mm < 4; mm++) {
            int m = mm*256 + tid;
            const float4* er = (const float4*)(emb + ((size_t)n*1024 + m)*128);
            float c = 0.f;
            #pragma unroll 8
            for (int qq = 0; qq < 32; qq++) {   // ascending-d sequential fmaf chain
                float4 e4 = er[qq];
                c = fmaf(xs[qq*4+0], e4.x, c);
                c = fmaf(xs[qq*4+1], e4.y, c);
                c = fmaf(xs[qq*4+2], e4.z, c);
                c = fmaf(xs[qq*4+3], e4.w, c);
            }
            float D = __fsub_rn(__fadd_rn(g_esq[n*1024 + m], xsq), 2.f*c);
            if (D < bD || (D == bD && m < bM)) { bD = D; bM = m; }
        }
        sD[tid] = bD; sM[tid] = bM;
        __syncthreads();
        for (int st = 128; st; st >>= 1) {
            if (tid < st) {
                float oD = sD[tid+st]; int oM = sM[tid+st];
                if (oD < sD[tid] || (oD == sD[tid] && oM < sM[tid])) { sD[tid] = oD; sM[tid] = oM; }
            }
            __syncthreads();
        }
        if (tid == 0) g_indices[n*LPER + l] = sM[0];
    }
}

// ---------------- gather + z_q + loss partials + indices out ----------------
__global__ void __launch_bounds__(256)
gather_kernel(const float* __restrict__ x, const float* __restrict__ emb,
              float* __restrict__ out, float* __restrict__ out_idx, int write_extras) {
    __shared__ int   midx[64];
    __shared__ float rows[64*129];
    __shared__ float red[256];
    const int n = blockIdx.x & 7, b = blockIdx.x >> 3, tid = threadIdx.x;

    if (tid < 64) {
        int m = g_indices[n*LPER + b*HLAT + tid];
        midx[tid] = m;
        if (write_extras) out_idx[b*(NCB*HLAT) + n*HLAT + tid] = (float)m;
    }
    __syncthreads();
    for (int idx = tid; idx < 64*128; idx += 256) {
        int r = idx >> 7, d = idx & 127;
        rows[r*129 + d] = emb[(size_t)n*(MEMB*DEMB) + (size_t)midx[r]*DEMB + d];
    }
    __syncthreads();
    float s = 0.f;
    const size_t base = (size_t)b*65536 + (size_t)n*8192;
    for (int idx = tid; idx < 8192; idx += 256) {
        int d = idx >> 6, h = idx & 63;
        float q  = rows[h*129 + d];
        float xv = x[base + idx];
        out[base + idx] = q;
        float df = xv - q;
        s += df*df;
    }
    red[tid] = s;
    __syncthreads();
    for (int st = 128; st; st >>= 1) { if (tid < st) red[tid] += red[tid+st]; __syncthreads(); }
    if (tid == 0) g_part[blockIdx.x] = red[0];
}

// ---------------- entropy ----------------
__global__ void entropy_kernel() {
    __shared__ int   hist[MEMB];
    __shared__ float red[256];
    const int n = blockIdx.x, tid = threadIdx.x;
    for (int i = tid; i < MEMB; i += 256) hist[i] = 0;
    __syncthreads();
    for (int l = tid; l < LPER; l += 256) atomicAdd(&hist[g_indices[n*LPER + l]], 1);
    __syncthreads();
    float s = 0.f;
    for (int m = tid; m < MEMB; m += 256) {
        float p = (float)hist[m] * (1.f / (float)LPER);
        s += p * logf(p + 1e-10f);
    }
    red[tid] = s;
    __syncthreads();
    for (int st = 128; st; st >>= 1) { if (tid < st) red[tid] += red[tid+st]; __syncthreads(); }
    if (tid == 0) g_ent[n] = -red[0];
}

// ---------------- finalize ----------------
__global__ void finalize_kernel(float* __restrict__ out, int write_scalars) {
    __shared__ float red[256];
    const int tid = threadIdx.x;
    float s = 0.f;
    for (int i = tid; i < 2048; i += 256) s += g_part[i];
    red[tid] = s;
    __syncthreads();
    for (int st = 128; st; st >>= 1) { if (tid < st) red[tid] += red[tid+st]; __syncthreads(); }
    if (tid == 0 && write_scalars) {
        float loss = 0.25f * red[0] / (float)ZQ_ELEMS;
        float ent = 0.f, perp = 0.f;
        #pragma unroll
        for (int n = 0; n < NCB; n++) { ent += g_ent[n]; perp += expf(g_ent[n]); }
        out[ZQ_ELEMS + 0] = loss;
        out[ZQ_ELEMS + 1] = ent * (1.f / NCB);
        out[ZQ_ELEMS + 2] = perp * (1.f / NCB);
    }
}

// ---------------- launch ----------------
extern "C" void kernel_launch(void* const* d_in, const int* in_sizes, int n_in,
                              void* d_out, int out_size) {
    const float* x   = (const float*)d_in[0];
    const float* emb = (const float*)d_in[1];
    if (n_in >= 2 && in_sizes[0] == NCB*MEMB*DEMB && in_sizes[1] == ZQ_ELEMS) {
        const float* t = x; x = emb; emb = t;
    }
    float* out = (float*)d_out;
    const int full = (out_size >= ZQ_ELEMS + 3 + IDX_ELEMS) ? 1 : 0;

    const int SMEM_ARG = 138240 + 1024;
    cudaFuncSetAttribute(argmin_mma, cudaFuncAttributeMaxDynamicSharedMemorySize, SMEM_ARG);

    esq_kernel<<<(NCB*MEMB + 255)/256, 256>>>(emb);
    xsq_kernel<<<BATCH*NCB, 256>>>(x);
    bprep_kernel<<<(NCB*MEMB*DEMB + 255)/256, 256>>>(emb);
    argmin_mma<<<NCB * (LPER/128), 256, SMEM_ARG>>>(x);
    fixup_kernel<<<512, 256>>>(x, emb);
    gather_kernel<<<BATCH*NCB, 256>>>(x, emb, out, out + ZQ_ELEMS + 3, full);
    entropy_kernel<<<NCB, 256>>>();
    finalize_kernel<<<1, 256>>>(out, full);
}

// round 5
// speedup vs baseline: 1.8893x; 1.6715x over previous
#include <cuda_runtime.h>
#include <cuda_bf16.h>
#include <math.h>
#include <stdint.h>

#define NCB   8
#define MEMB  1024
#define DEMB  128
#define HLAT  64
#define BATCH 256
#define LPER  (BATCH*HLAT)              /* 16384 per codebook */
#define ZQ_ELEMS (BATCH*NCB*DEMB*HLAT)  /* 16777216 */
#define IDX_ELEMS (BATCH*NCB*HLAT)      /* 131072 */
#define MARGIN 6e-5f

// ---------------- device scratch ----------------
__device__ int   g_indices[NCB*LPER];
__device__ float g_esq[NCB*MEMB];
__device__ float g_xsq[NCB*LPER];
__device__ float g_part[2048];
__device__ float g_ent[NCB];
__device__ int   g_ucount;
__device__ int   g_ulist[NCB*LPER];
// pre-swizzled bf16 embedding tiles: [n][mchunk 8][row 128][k 128], 16B-chunk XOR swizzle
__device__ __nv_bfloat16 g_bhi[NCB*MEMB*DEMB];
__device__ __nv_bfloat16 g_blo[NCB*MEMB*DEMB];

// ---------------- PTX helpers ----------------
__device__ __forceinline__ uint32_t smem_u32(const void* p) {
    uint32_t a;
    asm("{ .reg .u64 t; cvta.to.shared.u64 t, %1; cvt.u32.u64 %0, t; }" : "=r"(a) : "l"(p));
    return a;
}
__device__ __forceinline__ void ldsm4(uint32_t* r, uint32_t addr) {
    asm volatile("ldmatrix.sync.aligned.m8n8.x4.shared.b16 {%0,%1,%2,%3}, [%4];"
        : "=r"(r[0]), "=r"(r[1]), "=r"(r[2]), "=r"(r[3]) : "r"(addr));
}
__device__ __forceinline__ void mma_bf16(float* c, const uint32_t* a, const uint32_t* b) {
    asm volatile("mma.sync.aligned.m16n8k16.row.col.f32.bf16.bf16.f32 "
        "{%0,%1,%2,%3}, {%4,%5,%6,%7}, {%8,%9}, {%0,%1,%2,%3};"
        : "+f"(c[0]), "+f"(c[1]), "+f"(c[2]), "+f"(c[3])
        : "r"(a[0]), "r"(a[1]), "r"(a[2]), "r"(a[3]), "r"(b[0]), "r"(b[1]));
}
__device__ __forceinline__ void cp16(uint32_t dst, const void* src) {
    asm volatile("cp.async.cg.shared.global [%0], [%1], 16;" :: "r"(dst), "l"(src) : "memory");
}
#define CP_COMMIT() asm volatile("cp.async.commit_group;" ::: "memory")
#define CP_WAIT(n)  asm volatile("cp.async.wait_group %0;" :: "n"(n) : "memory")

// ---------------- e_sq (exact sequential) + ucount reset ----------------
__global__ void esq_kernel(const float* __restrict__ emb) {
    int t = blockIdx.x * blockDim.x + threadIdx.x;
    if (t == 0) g_ucount = 0;
    if (t >= NCB*MEMB) return;
    const float* row = emb + (size_t)t * DEMB;
    float acc = 0.f;
    #pragma unroll 8
    for (int d = 0; d < DEMB; d++) {
        float v = row[d];
        acc = __fadd_rn(acc, __fmul_rn(v, v));
    }
    g_esq[t] = acc;
}

// ---------------- x_sq (exact sequential) ----------------
__global__ void __launch_bounds__(256)
xsq_kernel(const float* __restrict__ x) {
    __shared__ float tile[8192];
    const int n = blockIdx.x & 7, b = blockIdx.x >> 3, tid = threadIdx.x;
    const size_t base = (size_t)b*65536 + (size_t)n*8192;
    for (int i = tid; i < 8192; i += 256) tile[i] = x[base + i];
    __syncthreads();
    if (tid < 64) {
        float acc = 0.f;
        #pragma unroll 8
        for (int d = 0; d < DEMB; d++) {
            float v = tile[d*64 + tid];
            acc = __fadd_rn(acc, __fmul_rn(v, v));
        }
        g_xsq[n*LPER + b*HLAT + tid] = acc;
    }
}

// ---------------- embedding -> swizzled bf16 hi/lo tiles ----------------
__global__ void bprep_kernel(const float* __restrict__ emb) {
    int u = blockIdx.x * blockDim.x + threadIdx.x;
    if (u >= NCB*MEMB*DEMB) return;
    float v = emb[u];
    int d = u & 127, m = (u >> 7) & 1023, n = u >> 17;
    __nv_bfloat16 h = __float2bfloat16(v);
    __nv_bfloat16 l = __float2bfloat16(v - __bfloat162float(h));
    int row = m & 127, mc = m >> 7;
    int elem = ((n*8 + mc)*128 + row)*128 + (((d >> 3) ^ (row & 7)) << 3) + (d & 7);
    g_bhi[elem] = h;
    g_blo[elem] = l;
}

// ---------------- pass 1: tensor-core (mma.sync) approximate argmin ----------------
// A[l=128,k=128] bf16 hi/lo in smem; B chunks double-buffered via cp.async.
// C = A.B^T f32, 3 combos (hh+hl+lh) into the same accumulator.
__global__ void __launch_bounds__(256, 1)
argmin_mma(const float* __restrict__ x) {
    extern __shared__ char smraw[];
    uint32_t sraw = smem_u32(smraw);
    uint32_t sb = (sraw + 1023u) & ~1023u;
    char* sm = smraw + (sb - sraw);
    __nv_bfloat16* Ahi = (__nv_bfloat16*)(sm);            // 32KB @0
    __nv_bfloat16* Alo = (__nv_bfloat16*)(sm + 32768);    // 32KB
    // B buffers: buf0 @65536 (hi 32KB, lo 32KB), buf1 @131072
    float* esq_s = (float*)(sm + 196608);                 // 4KB
    float* sbest = (float*)(sm + 200704);
    float* ssec  = (float*)(sm + 201728);
    int*   sidx  = (int*)  (sm + 202752);

    const int n  = blockIdx.x >> 7;
    const int lt = blockIdx.x & 127;
    const int l0 = lt * 128;
    const int b0 = lt * 2;
    const int tid  = threadIdx.x;
    const int lane = tid & 31;
    const int w    = tid >> 5;
    const int wl   = w & 3;     // l quarter (32 rows)
    const int wm   = w >> 2;    // m half (64 cols)

    // ---- prefetch B chunk 0 into buf0 (overlaps with A staging) ----
    {
        const char* srcHi = (const char*)(g_bhi + ((size_t)(n*8 + 0) << 14));
        const char* srcLo = (const char*)(g_blo + ((size_t)(n*8 + 0) << 14));
        uint32_t dstHi = sb + 65536, dstLo = sb + 65536 + 32768;
        #pragma unroll
        for (int i = 0; i < 8; i++) {
            cp16(dstHi + (tid + i*256)*16, srcHi + (tid + i*256)*16);
            cp16(dstLo + (tid + i*256)*16, srcLo + (tid + i*256)*16);
        }
        CP_COMMIT();
    }

    // stage e_sq
    for (int i = tid; i < 1024; i += 256) esq_s[i] = g_esq[n*1024 + i];

    // stage + split-convert A tile (swizzled)
    for (int idx = tid; idx < 16384; idx += 256) {
        int d = idx >> 7, j = idx & 127;
        float v = x[(size_t)(b0 + (j >> 6))*65536 + (size_t)n*8192 + d*64 + (j & 63)];
        __nv_bfloat16 h = __float2bfloat16(v);
        __nv_bfloat16 l = __float2bfloat16(v - __bfloat162float(h));
        int elem = j*128 + (((d >> 3) ^ (j & 7)) << 3) + (d & 7);
        Ahi[elem] = h; Alo[elem] = l;
    }

    // ldmatrix per-lane address precompute
    const uint32_t sAh = sb, sBh0 = sb + 65536;
    const int q  = lane >> 3;
    const int r8 = lane & 7;
    const int cqA = q >> 1;
    const int cqB = q & 1;
    uint32_t aBase[2]; int a7[2];
    #pragma unroll
    for (int t2 = 0; t2 < 2; t2++) {
        int rowA = wl*32 + t2*16 + r8 + (q & 1)*8;
        aBase[t2] = sAh + rowA*256; a7[t2] = rowA & 7;
    }
    uint32_t bBase[4]; int b7[4];
    #pragma unroll
    for (int p = 0; p < 4; p++) {
        int rowB = wm*64 + p*16 + r8 + (q >> 1)*8;
        bBase[p] = sBh0 + rowB*256; b7[p] = rowB & 7;
    }

    float best[4], sec[4];
    int   idxm[4];
    #pragma unroll
    for (int s = 0; s < 4; s++) { best[s] = 3.4e38f; sec[s] = 3.4e38f; idxm[s] = 0; }

    const int col2 = (lane & 3) * 2;

    for (int mc = 0; mc < 8; mc++) {
        // prefetch next chunk into the other buffer, then wait for current
        if (mc < 7) {
            const char* srcHi = (const char*)(g_bhi + ((size_t)(n*8 + mc + 1) << 14));
            const char* srcLo = (const char*)(g_blo + ((size_t)(n*8 + mc + 1) << 14));
            uint32_t dbuf = sb + 65536 + (uint32_t)(((mc + 1) & 1) * 65536);
            #pragma unroll
            for (int i = 0; i < 8; i++) {
                cp16(dbuf + (tid + i*256)*16,         srcHi + (tid + i*256)*16);
                cp16(dbuf + 32768 + (tid + i*256)*16, srcLo + (tid + i*256)*16);
            }
            CP_COMMIT();
            CP_WAIT(1);
        } else {
            CP_WAIT(0);
        }
        __syncthreads();   // current buffer visible to all (also covers A on mc=0)

        const uint32_t bufOff = (uint32_t)((mc & 1) * 65536);

        float acc[2][8][4];
        #pragma unroll
        for (int t2 = 0; t2 < 2; t2++)
            #pragma unroll
            for (int mt = 0; mt < 8; mt++)
                #pragma unroll
                for (int c = 0; c < 4; c++) acc[t2][mt][c] = 0.f;

        #pragma unroll
        for (int ks = 0; ks < 8; ks++) {
            const int ks2 = ks * 2;
            uint32_t ah[2][4], al[2][4];
            #pragma unroll
            for (int t2 = 0; t2 < 2; t2++) {
                uint32_t off = (uint32_t)(((ks2 + cqA) ^ a7[t2]) << 4);
                ldsm4(ah[t2], aBase[t2] + off);
                ldsm4(al[t2], aBase[t2] + off + 32768);
            }
            uint32_t bh[4][4], bl[4][4];
            #pragma unroll
            for (int p = 0; p < 4; p++) {
                uint32_t off = (uint32_t)(((ks2 + cqB) ^ b7[p]) << 4) + bufOff;
                ldsm4(bh[p], bBase[p] + off);
                ldsm4(bl[p], bBase[p] + off + 32768);
            }
            #pragma unroll
            for (int t2 = 0; t2 < 2; t2++)
                #pragma unroll
                for (int p = 0; p < 4; p++) {
                    mma_bf16(acc[t2][2*p],   ah[t2], &bh[p][0]);
                    mma_bf16(acc[t2][2*p+1], ah[t2], &bh[p][2]);
                    mma_bf16(acc[t2][2*p],   ah[t2], &bl[p][0]);
                    mma_bf16(acc[t2][2*p+1], ah[t2], &bl[p][2]);
                    mma_bf16(acc[t2][2*p],   al[t2], &bh[p][0]);
                    mma_bf16(acc[t2][2*p+1], al[t2], &bh[p][2]);
                }
        }

        // epilogue: t = e_sq - 2*dot ; update best/second
        const int mbase = mc*128 + wm*64;
        #pragma unroll
        for (int t2 = 0; t2 < 2; t2++) {
            #pragma unroll
            for (int mt = 0; mt < 8; mt++) {
                float e0 = esq_s[mbase + mt*8 + col2];
                float e1 = esq_s[mbase + mt*8 + col2 + 1];
                int m0 = mbase + mt*8 + col2;
                {
                    int s = t2*2;
                    float ta = e0 - 2.f*acc[t2][mt][0];
                    float tb = e1 - 2.f*acc[t2][mt][1];
                    if (ta < best[s]) { sec[s] = best[s]; best[s] = ta; idxm[s] = m0; }
                    else if (ta < sec[s]) sec[s] = ta;
                    if (tb < best[s]) { sec[s] = best[s]; best[s] = tb; idxm[s] = m0 + 1; }
                    else if (tb < sec[s]) sec[s] = tb;
                }
                {
                    int s = t2*2 + 1;
                    float ta = e0 - 2.f*acc[t2][mt][2];
                    float tb = e1 - 2.f*acc[t2][mt][3];
                    if (ta < best[s]) { sec[s] = best[s]; best[s] = ta; idxm[s] = m0; }
                    else if (ta < sec[s]) sec[s] = ta;
                    if (tb < best[s]) { sec[s] = best[s]; best[s] = tb; idxm[s] = m0 + 1; }
                    else if (tb < sec[s]) sec[s] = tb;
                }
            }
        }
        __syncthreads();   // all warps done reading this buffer before overwrite
    }

    // quad reduce (lanes sharing lane>>2 hold the same rows)
    #pragma unroll
    for (int s = 0; s < 4; s++) {
        float b = best[s], sc = sec[s];
        int   im = idxm[s];
        #pragma unroll
        for (int off = 1; off <= 2; off <<= 1) {
            float ob = __shfl_xor_sync(0xffffffffu, b,  off);
            float os = __shfl_xor_sync(0xffffffffu, sc, off);
            int   oi = __shfl_xor_sync(0xffffffffu, im, off);
            if (ob < b || (ob == b && oi < im)) {
                sc = fminf(b, os); b = ob; im = oi;
            } else {
                sc = fminf(sc, ob);
            }
        }
        best[s] = b; sec[s] = sc; idxm[s] = im;
    }
    if ((lane & 3) == 0) {
        const int g = lane >> 2;
        #pragma unroll
        for (int s = 0; s < 4; s++) {
            int row = wl*32 + (s >> 1)*16 + g + (s & 1)*8;
            sbest[wm*128 + row] = best[s];
            ssec [wm*128 + row] = sec[s];
            sidx [wm*128 + row] = idxm[s];
        }
    }
    __syncthreads();

    if (tid < 128) {
        float b0f = sbest[tid],        b1f = sbest[128 + tid];
        float s0f = ssec[tid],         s1f = ssec[128 + tid];
        int   i0  = sidx[tid],         i1  = sidx[128 + tid];
        float b, s; int im;
        if (b1f < b0f || (b1f == b0f && i1 < i0)) { b = b1f; im = i1; s = fminf(b0f, s1f); }
        else { b = b0f; im = i0; s = fminf(s0f, b1f); }
        int l = l0 + tid;
        g_indices[n*LPER + l] = im;
        if (s - b < MARGIN) {
            int p = atomicAdd(&g_ucount, 1);
            g_ulist[p] = (n << 14) | l;
        }
    }
}

// ---------------- pass 2: exact rescan of uncertain rows ----------------
__global__ void __launch_bounds__(256)
fixup_kernel(const float* __restrict__ x, const float* __restrict__ emb) {
    __shared__ float xs[128];
    __shared__ float sD[256];
    __shared__ int   sM[256];
    const int tid = threadIdx.x;
    const int cnt = g_ucount;
    for (int u = blockIdx.x; u < cnt; u += gridDim.x) {
        int id = g_ulist[u];
        int n = id >> 14, l = id & 16383;
        int b = l >> 6, h = l & 63;
        __syncthreads();
        if (tid < 128) xs[tid] = x[(size_t)b*65536 + (size_t)n*8192 + tid*64 + h];
        __syncthreads();
        float xsq = g_xsq[n*LPER + l];
        float bD = 3.4e38f; int bM = 0;
        for (int mm = 0; mm < 4; mm++) {
            int m = mm*256 + tid;
            const float4* er = (const float4*)(emb + ((size_t)n*1024 + m)*128);
            float c = 0.f;
            #pragma unroll 8
            for (int qq = 0; qq < 32; qq++) {   // ascending-d sequential fmaf chain
                float4 e4 = er[qq];
                c = fmaf(xs[qq*4+0], e4.x, c);
                c = fmaf(xs[qq*4+1], e4.y, c);
                c = fmaf(xs[qq*4+2], e4.z, c);
                c = fmaf(xs[qq*4+3], e4.w, c);
            }
            float D = __fsub_rn(__fadd_rn(g_esq[n*1024 + m], xsq), 2.f*c);
            if (D < bD || (D == bD && m < bM)) { bD = D; bM = m; }
        }
        sD[tid] = bD; sM[tid] = bM;
        __syncthreads();
        for (int st = 128; st; st >>= 1) {
            if (tid < st) {
                float oD = sD[tid+st]; int oM = sM[tid+st];
                if (oD < sD[tid] || (oD == sD[tid] && oM < sM[tid])) { sD[tid] = oD; sM[tid] = oM; }
            }
            __syncthreads();
        }
        if (tid == 0) g_indices[n*LPER + l] = sM[0];
    }
}

// ---------------- gather + z_q + loss partials + indices out ----------------
__global__ void __launch_bounds__(256)
gather_kernel(const float* __restrict__ x, const float* __restrict__ emb,
              float* __restrict__ out, float* __restrict__ out_idx, int write_extras) {
    __shared__ int   midx[64];
    __shared__ float rows[64*129];
    __shared__ float red[256];
    const int n = blockIdx.x & 7, b = blockIdx.x >> 3, tid = threadIdx.x;

    if (tid < 64) {
        int m = g_indices[n*LPER + b*HLAT + tid];
        midx[tid] = m;
        if (write_extras) out_idx[b*(NCB*HLAT) + n*HLAT + tid] = (float)m;
    }
    __syncthreads();
    for (int idx = tid; idx < 64*128; idx += 256) {
        int r = idx >> 7, d = idx & 127;
        rows[r*129 + d] = emb[(size_t)n*(MEMB*DEMB) + (size_t)midx[r]*DEMB + d];
    }
    __syncthreads();
    float s = 0.f;
    const size_t base = (size_t)b*65536 + (size_t)n*8192;
    for (int idx = tid; idx < 8192; idx += 256) {
        int d = idx >> 6, h = idx & 63;
        float q  = rows[h*129 + d];
        float xv = x[base + idx];
        out[base + idx] = q;
        float df = xv - q;
        s += df*df;
    }
    red[tid] = s;
    __syncthreads();
    for (int st = 128; st; st >>= 1) { if (tid < st) red[tid] += red[tid+st]; __syncthreads(); }
    if (tid == 0) g_part[blockIdx.x] = red[0];
}

// ---------------- entropy ----------------
__global__ void entropy_kernel() {
    __shared__ int   hist[MEMB];
    __shared__ float red[256];
    const int n = blockIdx.x, tid = threadIdx.x;
    for (int i = tid; i < MEMB; i += 256) hist[i] = 0;
    __syncthreads();
    for (int l = tid; l < LPER; l += 256) atomicAdd(&hist[g_indices[n*LPER + l]], 1);
    __syncthreads();
    float s = 0.f;
    for (int m = tid; m < MEMB; m += 256) {
        float p = (float)hist[m] * (1.f / (float)LPER);
        s += p * logf(p + 1e-10f);
    }
    red[tid] = s;
    __syncthreads();
    for (int st = 128; st; st >>= 1) { if (tid < st) red[tid] += red[tid+st]; __syncthreads(); }
    if (tid == 0) g_ent[n] = -red[0];
}

// ---------------- finalize ----------------
__global__ void finalize_kernel(float* __restrict__ out, int write_scalars) {
    __shared__ float red[256];
    const int tid = threadIdx.x;
    float s = 0.f;
    for (int i = tid; i < 2048; i += 256) s += g_part[i];
    red[tid] = s;
    __syncthreads();
    for (int st = 128; st; st >>= 1) { if (tid < st) red[tid] += red[tid+st]; __syncthreads(); }
    if (tid == 0 && write_scalars) {
        float loss = 0.25f * red[0] / (float)ZQ_ELEMS;
        float ent = 0.f, perp = 0.f;
        #pragma unroll
        for (int n = 0; n < NCB; n++) { ent += g_ent[n]; perp += expf(g_ent[n]); }
        out[ZQ_ELEMS + 0] = loss;
        out[ZQ_ELEMS + 1] = ent * (1.f / NCB);
        out[ZQ_ELEMS + 2] = perp * (1.f / NCB);
    }
}

// ---------------- launch ----------------
extern "C" void kernel_launch(void* const* d_in, const int* in_sizes, int n_in,
                              void* d_out, int out_size) {
    const float* x   = (const float*)d_in[0];
    const float* emb = (const float*)d_in[1];
    if (n_in >= 2 && in_sizes[0] == NCB*MEMB*DEMB && in_sizes[1] == ZQ_ELEMS) {
        const float* t = x; x = emb; emb = t;
    }
    float* out = (float*)d_out;
    const int full = (out_size >= ZQ_ELEMS + 3 + IDX_ELEMS) ? 1 : 0;

    const int SMEM_ARG = 203776 + 1024;
    cudaFuncSetAttribute(argmin_mma, cudaFuncAttributeMaxDynamicSharedMemorySize, SMEM_ARG);

    esq_kernel<<<(NCB*MEMB + 255)/256, 256>>>(emb);
    xsq_kernel<<<BATCH*NCB, 256>>>(x);
    bprep_kernel<<<(NCB*MEMB*DEMB + 255)/256, 256>>>(emb);
    argmin_mma<<<NCB * (LPER/128), 256, SMEM_ARG>>>(x);
    fixup_kernel<<<512, 256>>>(x, emb);
    gather_kernel<<<BATCH*NCB, 256>>>(x, emb, out, out + ZQ_ELEMS + 3, full);
    entropy_kernel<<<NCB, 256>>>();
    finalize_kernel<<<1, 256>>>(out, full);
}

// round 6
// speedup vs baseline: 2.0937x; 1.1082x over previous
#include <cuda_runtime.h>
#include <cuda_bf16.h>
#include <math.h>
#include <stdint.h>

#define NCB   8
#define MEMB  1024
#define DEMB  128
#define HLAT  64
#define BATCH 256
#define LPER  (BATCH*HLAT)              /* 16384 per codebook */
#define ZQ_ELEMS (BATCH*NCB*DEMB*HLAT)  /* 16777216 */
#define IDX_ELEMS (BATCH*NCB*HLAT)      /* 131072 */
#define MARGIN 6e-5f

// ---------------- device scratch ----------------
__device__ int   g_indices[NCB*LPER];
__device__ float g_esq[NCB*MEMB];
__device__ float g_xsq[NCB*LPER];
__device__ float g_part[2048];
__device__ float g_ent[NCB];
__device__ int   g_ucount;
__device__ int   g_ulist[NCB*LPER];
// pre-swizzled bf16 embedding tiles: [n][mchunk 8][row 128][k 128], 16B-chunk XOR swizzle
__device__ __nv_bfloat16 g_bhi[NCB*MEMB*DEMB];
__device__ __nv_bfloat16 g_blo[NCB*MEMB*DEMB];

// ---------------- PTX helpers ----------------
__device__ __forceinline__ uint32_t smem_u32(const void* p) {
    uint32_t a;
    asm("{ .reg .u64 t; cvta.to.shared.u64 t, %1; cvt.u32.u64 %0, t; }" : "=r"(a) : "l"(p));
    return a;
}
__device__ __forceinline__ void ldsm4(uint32_t* r, uint32_t addr) {
    asm volatile("ldmatrix.sync.aligned.m8n8.x4.shared.b16 {%0,%1,%2,%3}, [%4];"
        : "=r"(r[0]), "=r"(r[1]), "=r"(r[2]), "=r"(r[3]) : "r"(addr));
}
__device__ __forceinline__ void mma_bf16(float* c, const uint32_t* a, const uint32_t* b) {
    asm volatile("mma.sync.aligned.m16n8k16.row.col.f32.bf16.bf16.f32 "
        "{%0,%1,%2,%3}, {%4,%5,%6,%7}, {%8,%9}, {%0,%1,%2,%3};"
        : "+f"(c[0]), "+f"(c[1]), "+f"(c[2]), "+f"(c[3])
        : "r"(a[0]), "r"(a[1]), "r"(a[2]), "r"(a[3]), "r"(b[0]), "r"(b[1]));
}
__device__ __forceinline__ void cp16(uint32_t dst, const void* src) {
    asm volatile("cp.async.cg.shared.global [%0], [%1], 16;" :: "r"(dst), "l"(src) : "memory");
}
#define CP_COMMIT() asm volatile("cp.async.commit_group;" ::: "memory")
#define CP_WAIT(n)  asm volatile("cp.async.wait_group %0;" :: "n"(n) : "memory")

// ---------------- e_sq (exact sequential) + ucount reset ----------------
__global__ void esq_kernel(const float* __restrict__ emb) {
    int t = blockIdx.x * blockDim.x + threadIdx.x;
    if (t == 0) g_ucount = 0;
    if (t >= NCB*MEMB) return;
    const float* row = emb + (size_t)t * DEMB;
    float acc = 0.f;
    #pragma unroll 8
    for (int d = 0; d < DEMB; d++) {
        float v = row[d];
        acc = __fadd_rn(acc, __fmul_rn(v, v));
    }
    g_esq[t] = acc;
}

// ---------------- x_sq (exact sequential) ----------------
__global__ void __launch_bounds__(256)
xsq_kernel(const float* __restrict__ x) {
    __shared__ float tile[8192];
    const int n = blockIdx.x & 7, b = blockIdx.x >> 3, tid = threadIdx.x;
    const size_t base = (size_t)b*65536 + (size_t)n*8192;
    for (int i = tid; i < 8192; i += 256) tile[i] = x[base + i];
    __syncthreads();
    if (tid < 64) {
        float acc = 0.f;
        #pragma unroll 8
        for (int d = 0; d < DEMB; d++) {
            float v = tile[d*64 + tid];
            acc = __fadd_rn(acc, __fmul_rn(v, v));
        }
        g_xsq[n*LPER + b*HLAT + tid] = acc;
    }
}

// ---------------- embedding -> swizzled bf16 hi/lo tiles ----------------
__global__ void bprep_kernel(const float* __restrict__ emb) {
    int u = blockIdx.x * blockDim.x + threadIdx.x;
    if (u >= NCB*MEMB*DEMB) return;
    float v = emb[u];
    int d = u & 127, m = (u >> 7) & 1023, n = u >> 17;
    __nv_bfloat16 h = __float2bfloat16(v);
    __nv_bfloat16 l = __float2bfloat16(v - __bfloat162float(h));
    int row = m & 127, mc = m >> 7;
    int elem = ((n*8 + mc)*128 + row)*128 + (((d >> 3) ^ (row & 7)) << 3) + (d & 7);
    g_bhi[elem] = h;
    g_blo[elem] = l;
}

// ---------------- pass 1: tensor-core (mma.sync) approximate argmin ----------------
// 512 threads = 16 warps = 4(l) x 4(m); warp tile 32x32.
// A[l=128,k=128] bf16 hi/lo in smem; B chunks double-buffered via cp.async.
// C = A.B^T f32, 3 combos (hh+hl+lh) into the same accumulator.
__global__ void __launch_bounds__(512, 1)
argmin_mma(const float* __restrict__ x) {
    extern __shared__ char smraw[];
    uint32_t sraw = smem_u32(smraw);
    uint32_t sb = (sraw + 1023u) & ~1023u;
    char* sm = smraw + (sb - sraw);
    __nv_bfloat16* Ahi = (__nv_bfloat16*)(sm);            // 32KB @0
    __nv_bfloat16* Alo = (__nv_bfloat16*)(sm + 32768);    // 32KB
    // B buffers: buf0 @65536 (hi 32KB, lo 32KB), buf1 @131072
    float* esq_s = (float*)(sm + 196608);                 // 4KB
    float* sbest = (float*)(sm + 200704);                 // 512 f32
    float* ssec  = (float*)(sm + 202752);                 // 512 f32
    int*   sidx  = (int*)  (sm + 204800);                 // 512 int

    const int n  = blockIdx.x >> 7;
    const int lt = blockIdx.x & 127;
    const int l0 = lt * 128;
    const int b0 = lt * 2;
    const int tid  = threadIdx.x;
    const int lane = tid & 31;
    const int w    = tid >> 5;
    const int wl   = w & 3;     // l quarter (32 rows)
    const int wm   = w >> 2;    // m quarter (32 cols)

    // ---- prefetch B chunk 0 into buf0 (overlaps with A staging) ----
    {
        const char* srcHi = (const char*)(g_bhi + ((size_t)(n*8 + 0) << 14));
        const char* srcLo = (const char*)(g_blo + ((size_t)(n*8 + 0) << 14));
        uint32_t dstHi = sb + 65536, dstLo = sb + 65536 + 32768;
        #pragma unroll
        for (int i = 0; i < 4; i++) {
            cp16(dstHi + (tid + i*512)*16, srcHi + (tid + i*512)*16);
            cp16(dstLo + (tid + i*512)*16, srcLo + (tid + i*512)*16);
        }
        CP_COMMIT();
    }

    // stage e_sq
    for (int i = tid; i < 1024; i += 512) esq_s[i] = g_esq[n*1024 + i];

    // stage + split-convert A tile (swizzled)
    for (int idx = tid; idx < 16384; idx += 512) {
        int d = idx >> 7, j = idx & 127;
        float v = x[(size_t)(b0 + (j >> 6))*65536 + (size_t)n*8192 + d*64 + (j & 63)];
        __nv_bfloat16 h = __float2bfloat16(v);
        __nv_bfloat16 l = __float2bfloat16(v - __bfloat162float(h));
        int elem = j*128 + (((d >> 3) ^ (j & 7)) << 3) + (d & 7);
        Ahi[elem] = h; Alo[elem] = l;
    }

    // ldmatrix per-lane address precompute
    const uint32_t sAh = sb, sBh0 = sb + 65536;
    const int q  = lane >> 3;
    const int r8 = lane & 7;
    const int cqA = q >> 1;
    const int cqB = q & 1;
    uint32_t aBase[2]; int a7[2];
    #pragma unroll
    for (int t2 = 0; t2 < 2; t2++) {
        int rowA = wl*32 + t2*16 + r8 + (q & 1)*8;
        aBase[t2] = sAh + rowA*256; a7[t2] = rowA & 7;
    }
    uint32_t bBase[2]; int b7[2];
    #pragma unroll
    for (int p = 0; p < 2; p++) {
        int rowB = wm*32 + p*16 + r8 + (q >> 1)*8;
        bBase[p] = sBh0 + rowB*256; b7[p] = rowB & 7;
    }

    float best[4], sec[4];
    int   idxm[4];
    #pragma unroll
    for (int s = 0; s < 4; s++) { best[s] = 3.4e38f; sec[s] = 3.4e38f; idxm[s] = 0; }

    const int col2 = (lane & 3) * 2;

    for (int mc = 0; mc < 8; mc++) {
        // prefetch next chunk into the other buffer, then wait for current
        if (mc < 7) {
            const char* srcHi = (const char*)(g_bhi + ((size_t)(n*8 + mc + 1) << 14));
            const char* srcLo = (const char*)(g_blo + ((size_t)(n*8 + mc + 1) << 14));
            uint32_t dbuf = sb + 65536 + (uint32_t)(((mc + 1) & 1) * 65536);
            #pragma unroll
            for (int i = 0; i < 4; i++) {
                cp16(dbuf + (tid + i*512)*16,         srcHi + (tid + i*512)*16);
                cp16(dbuf + 32768 + (tid + i*512)*16, srcLo + (tid + i*512)*16);
            }
            CP_COMMIT();
            CP_WAIT(1);
        } else {
            CP_WAIT(0);
        }
        __syncthreads();   // current buffer visible to all (also covers A on mc=0)

        const uint32_t bufOff = (uint32_t)((mc & 1) * 65536);

        float acc[2][4][4];
        #pragma unroll
        for (int t2 = 0; t2 < 2; t2++)
            #pragma unroll
            for (int mt = 0; mt < 4; mt++)
                #pragma unroll
                for (int c = 0; c < 4; c++) acc[t2][mt][c] = 0.f;

        #pragma unroll
        for (int ks = 0; ks < 8; ks++) {
            const int ks2 = ks * 2;
            uint32_t ah[2][4], al[2][4];
            #pragma unroll
            for (int t2 = 0; t2 < 2; t2++) {
                uint32_t off = (uint32_t)(((ks2 + cqA) ^ a7[t2]) << 4);
                ldsm4(ah[t2], aBase[t2] + off);
                ldsm4(al[t2], aBase[t2] + off + 32768);
            }
            uint32_t bh[2][4], bl[2][4];
            #pragma unroll
            for (int p = 0; p < 2; p++) {
                uint32_t off = (uint32_t)(((ks2 + cqB) ^ b7[p]) << 4) + bufOff;
                ldsm4(bh[p], bBase[p] + off);
                ldsm4(bl[p], bBase[p] + off + 32768);
            }
            #pragma unroll
            for (int t2 = 0; t2 < 2; t2++)
                #pragma unroll
                for (int p = 0; p < 2; p++) {
                    mma_bf16(acc[t2][2*p],   ah[t2], &bh[p][0]);
                    mma_bf16(acc[t2][2*p+1], ah[t2], &bh[p][2]);
                    mma_bf16(acc[t2][2*p],   ah[t2], &bl[p][0]);
                    mma_bf16(acc[t2][2*p+1], ah[t2], &bl[p][2]);
                    mma_bf16(acc[t2][2*p],   al[t2], &bh[p][0]);
                    mma_bf16(acc[t2][2*p+1], al[t2], &bh[p][2]);
                }
        }

        // epilogue: t = e_sq - 2*dot ; update best/second
        const int mbase = mc*128 + wm*32;
        #pragma unroll
        for (int t2 = 0; t2 < 2; t2++) {
            #pragma unroll
            for (int mt = 0; mt < 4; mt++) {
                float e0 = esq_s[mbase + mt*8 + col2];
                float e1 = esq_s[mbase + mt*8 + col2 + 1];
                int m0 = mbase + mt*8 + col2;
                {
                    int s = t2*2;
                    float ta = e0 - 2.f*acc[t2][mt][0];
                    float tb = e1 - 2.f*acc[t2][mt][1];
                    if (ta < best[s]) { sec[s] = best[s]; best[s] = ta; idxm[s] = m0; }
                    else if (ta < sec[s]) sec[s] = ta;
                    if (tb < best[s]) { sec[s] = best[s]; best[s] = tb; idxm[s] = m0 + 1; }
                    else if (tb < sec[s]) sec[s] = tb;
                }
                {
                    int s = t2*2 + 1;
                    float ta = e0 - 2.f*acc[t2][mt][2];
                    float tb = e1 - 2.f*acc[t2][mt][3];
                    if (ta < best[s]) { sec[s] = best[s]; best[s] = ta; idxm[s] = m0; }
                    else if (ta < sec[s]) sec[s] = ta;
                    if (tb < best[s]) { sec[s] = best[s]; best[s] = tb; idxm[s] = m0 + 1; }
                    else if (tb < sec[s]) sec[s] = tb;
                }
            }
        }
        __syncthreads();   // all warps done reading this buffer before overwrite
    }

    // quad reduce (lanes sharing lane>>2 hold the same rows)
    #pragma unroll
    for (int s = 0; s < 4; s++) {
        float b = best[s], sc = sec[s];
        int   im = idxm[s];
        #pragma unroll
        for (int off = 1; off <= 2; off <<= 1) {
            float ob = __shfl_xor_sync(0xffffffffu, b,  off);
            float os = __shfl_xor_sync(0xffffffffu, sc, off);
            int   oi = __shfl_xor_sync(0xffffffffu, im, off);
            if (ob < b || (ob == b && oi < im)) {
                sc = fminf(b, os); b = ob; im = oi;
            } else {
                sc = fminf(sc, ob);
            }
        }
        best[s] = b; sec[s] = sc; idxm[s] = im;
    }
    if ((lane & 3) == 0) {
        const int g = lane >> 2;
        #pragma unroll
        for (int s = 0; s < 4; s++) {
            int row = wl*32 + (s >> 1)*16 + g + (s & 1)*8;
            sbest[wm*128 + row] = best[s];
            ssec [wm*128 + row] = sec[s];
            sidx [wm*128 + row] = idxm[s];
        }
    }
    __syncthreads();

    if (tid < 128) {
        float b = sbest[tid], s = ssec[tid];
        int   im = sidx[tid];
        #pragma unroll
        for (int qq = 1; qq < 4; qq++) {
            float bq = sbest[qq*128 + tid];
            float sq = ssec [qq*128 + tid];
            int   iq = sidx [qq*128 + tid];
            if (bq < b || (bq == b && iq < im)) { s = fminf(b, sq); b = bq; im = iq; }
            else { s = fminf(s, bq); }
        }
        int l = l0 + tid;
        g_indices[n*LPER + l] = im;
        if (s - b < MARGIN) {
            int p = atomicAdd(&g_ucount, 1);
            g_ulist[p] = (n << 14) | l;
        }
    }
}

// ---------------- pass 2: exact rescan of uncertain rows ----------------
__global__ void __launch_bounds__(256)
fixup_kernel(const float* __restrict__ x, const float* __restrict__ emb) {
    __shared__ float xs[128];
    __shared__ float sD[256];
    __shared__ int   sM[256];
    const int tid = threadIdx.x;
    const int cnt = g_ucount;
    for (int u = blockIdx.x; u < cnt; u += gridDim.x) {
        int id = g_ulist[u];
        int n = id >> 14, l = id & 16383;
        int b = l >> 6, h = l & 63;
        __syncthreads();
        if (tid < 128) xs[tid] = x[(size_t)b*65536 + (size_t)n*8192 + tid*64 + h];
        __syncthreads();
        float xsq = g_xsq[n*LPER + l];
        float bD = 3.4e38f; int bM = 0;
        for (int mm = 0; mm < 4; mm++) {
            int m = mm*256 + tid;
            const float4* er = (const float4*)(emb + ((size_t)n*1024 + m)*128);
            float c = 0.f;
            #pragma unroll 8
            for (int qq = 0; qq < 32; qq++) {   // ascending-d sequential fmaf chain
                float4 e4 = er[qq];
                c = fmaf(xs[qq*4+0], e4.x, c);
                c = fmaf(xs[qq*4+1], e4.y, c);
                c = fmaf(xs[qq*4+2], e4.z, c);
                c = fmaf(xs[qq*4+3], e4.w, c);
            }
            float D = __fsub_rn(__fadd_rn(g_esq[n*1024 + m], xsq), 2.f*c);
            if (D < bD || (D == bD && m < bM)) { bD = D; bM = m; }
        }
        sD[tid] = bD; sM[tid] = bM;
        __syncthreads();
        for (int st = 128; st; st >>= 1) {
            if (tid < st) {
                float oD = sD[tid+st]; int oM = sM[tid+st];
                if (oD < sD[tid] || (oD == sD[tid] && oM < sM[tid])) { sD[tid] = oD; sM[tid] = oM; }
            }
            __syncthreads();
        }
        if (tid == 0) g_indices[n*LPER + l] = sM[0];
    }
}

// ---------------- gather + z_q + loss partials + indices out ----------------
__global__ void __launch_bounds__(256)
gather_kernel(const float* __restrict__ x, const float* __restrict__ emb,
              float* __restrict__ out, float* __restrict__ out_idx, int write_extras) {
    __shared__ int   midx[64];
    __shared__ float rows[64*129];
    __shared__ float red[256];
    const int n = blockIdx.x & 7, b = blockIdx.x >> 3, tid = threadIdx.x;

    if (tid < 64) {
        int m = g_indices[n*LPER + b*HLAT + tid];
        midx[tid] = m;
        if (write_extras) out_idx[b*(NCB*HLAT) + n*HLAT + tid] = (float)m;
    }
    __syncthreads();
    for (int idx = tid; idx < 64*128; idx += 256) {
        int r = idx >> 7, d = idx & 127;
        rows[r*129 + d] = emb[(size_t)n*(MEMB*DEMB) + (size_t)midx[r]*DEMB + d];
    }
    __syncthreads();
    float s = 0.f;
    const size_t base = (size_t)b*65536 + (size_t)n*8192;
    for (int idx = tid; idx < 8192; idx += 256) {
        int d = idx >> 6, h = idx & 63;
        float q  = rows[h*129 + d];
        float xv = x[base + idx];
        out[base + idx] = q;
        float df = xv - q;
        s += df*df;
    }
    red[tid] = s;
    __syncthreads();
    for (int st = 128; st; st >>= 1) { if (tid < st) red[tid] += red[tid+st]; __syncthreads(); }
    if (tid == 0) g_part[blockIdx.x] = red[0];
}

// ---------------- entropy ----------------
__global__ void entropy_kernel() {
    __shared__ int   hist[MEMB];
    __shared__ float red[256];
    const int n = blockIdx.x, tid = threadIdx.x;
    for (int i = tid; i < MEMB; i += 256) hist[i] = 0;
    __syncthreads();
    for (int l = tid; l < LPER; l += 256) atomicAdd(&hist[g_indices[n*LPER + l]], 1);
    __syncthreads();
    float s = 0.f;
    for (int m = tid; m < MEMB; m += 256) {
        float p = (float)hist[m] * (1.f / (float)LPER);
        s += p * logf(p + 1e-10f);
    }
    red[tid] = s;
    __syncthreads();
    for (int st = 128; st; st >>= 1) { if (tid < st) red[tid] += red[tid+st]; __syncthreads(); }
    if (tid == 0) g_ent[n] = -red[0];
}

// ---------------- finalize ----------------
__global__ void finalize_kernel(float* __restrict__ out, int write_scalars) {
    __shared__ float red[256];
    const int tid = threadIdx.x;
    float s = 0.f;
    for (int i = tid; i < 2048; i += 256) s += g_part[i];
    red[tid] = s;
    __syncthreads();
    for (int st = 128; st; st >>= 1) { if (tid < st) red[tid] += red[tid+st]; __syncthreads(); }
    if (tid == 0 && write_scalars) {
        float loss = 0.25f * red[0] / (float)ZQ_ELEMS;
        float ent = 0.f, perp = 0.f;
        #pragma unroll
        for (int n = 0; n < NCB; n++) { ent += g_ent[n]; perp += expf(g_ent[n]); }
        out[ZQ_ELEMS + 0] = loss;
        out[ZQ_ELEMS + 1] = ent * (1.f / NCB);
        out[ZQ_ELEMS + 2] = perp * (1.f / NCB);
    }
}

// ---------------- launch ----------------
extern "C" void kernel_launch(void* const* d_in, const int* in_sizes, int n_in,
                              void* d_out, int out_size) {
    const float* x   = (const float*)d_in[0];
    const float* emb = (const float*)d_in[1];
    if (n_in >= 2 && in_sizes[0] == NCB*MEMB*DEMB && in_sizes[1] == ZQ_ELEMS) {
        const float* t = x; x = emb; emb = t;
    }
    float* out = (float*)d_out;
    const int full = (out_size >= ZQ_ELEMS + 3 + IDX_ELEMS) ? 1 : 0;

    const int SMEM_ARG = 206848 + 1024;
    cudaFuncSetAttribute(argmin_mma, cudaFuncAttributeMaxDynamicSharedMemorySize, SMEM_ARG);

    esq_kernel<<<(NCB*MEMB + 255)/256, 256>>>(emb);
    xsq_kernel<<<BATCH*NCB, 256>>>(x);
    bprep_kernel<<<(NCB*MEMB*DEMB + 255)/256, 256>>>(emb);
    argmin_mma<<<NCB * (LPER/128), 512, SMEM_ARG>>>(x);
    fixup_kernel<<<512, 256>>>(x, emb);
    gather_kernel<<<BATCH*NCB, 256>>>(x, emb, out, out + ZQ_ELEMS + 3, full);
    entropy_kernel<<<NCB, 256>>>();
    finalize_kernel<<<1, 256>>>(out, full);
}

// round 7
// speedup vs baseline: 2.1943x; 1.0480x over previous
#include <cuda_runtime.h>
#include <cuda_bf16.h>
#include <math.h>
#include <stdint.h>

#define NCB   8
#define MEMB  1024
#define DEMB  128
#define HLAT  64
#define BATCH 256
#define LPER  (BATCH*HLAT)              /* 16384 per codebook */
#define ZQ_ELEMS (BATCH*NCB*DEMB*HLAT)  /* 16777216 */
#define IDX_ELEMS (BATCH*NCB*HLAT)      /* 131072 */
#define MARGIN 6e-5f

// ---------------- device scratch ----------------
__device__ int   g_indices[NCB*LPER];
__device__ float g_esq[NCB*MEMB];
__device__ float g_xsq[NCB*LPER];
__device__ float g_part[2048];
__device__ float g_ent[NCB];
__device__ int   g_ucount;
__device__ int   g_ulist[NCB*LPER];
// pre-swizzled bf16 embedding tiles: [n][mchunk 16][row 64][k 128], 16B-chunk XOR swizzle
__device__ __nv_bfloat16 g_bhi[NCB*MEMB*DEMB];
__device__ __nv_bfloat16 g_blo[NCB*MEMB*DEMB];

// ---------------- PTX helpers ----------------
__device__ __forceinline__ uint32_t smem_u32(const void* p) {
    uint32_t a;
    asm("{ .reg .u64 t; cvta.to.shared.u64 t, %1; cvt.u32.u64 %0, t; }" : "=r"(a) : "l"(p));
    return a;
}
__device__ __forceinline__ void ldsm4(uint32_t* r, uint32_t addr) {
    asm volatile("ldmatrix.sync.aligned.m8n8.x4.shared.b16 {%0,%1,%2,%3}, [%4];"
        : "=r"(r[0]), "=r"(r[1]), "=r"(r[2]), "=r"(r[3]) : "r"(addr));
}
__device__ __forceinline__ void mma_bf16(float* c, const uint32_t* a, const uint32_t* b) {
    asm volatile("mma.sync.aligned.m16n8k16.row.col.f32.bf16.bf16.f32 "
        "{%0,%1,%2,%3}, {%4,%5,%6,%7}, {%8,%9}, {%0,%1,%2,%3};"
        : "+f"(c[0]), "+f"(c[1]), "+f"(c[2]), "+f"(c[3])
        : "r"(a[0]), "r"(a[1]), "r"(a[2]), "r"(a[3]), "r"(b[0]), "r"(b[1]));
}
__device__ __forceinline__ void cp16(uint32_t dst, const void* src) {
    asm volatile("cp.async.cg.shared.global [%0], [%1], 16;" :: "r"(dst), "l"(src) : "memory");
}
#define CP_COMMIT() asm volatile("cp.async.commit_group;" ::: "memory")
#define CP_WAIT(n)  asm volatile("cp.async.wait_group %0;" :: "n"(n) : "memory")

// ---------------- e_sq (exact sequential) + ucount reset ----------------
__global__ void esq_kernel(const float* __restrict__ emb) {
    int t = blockIdx.x * blockDim.x + threadIdx.x;
    if (t == 0) g_ucount = 0;
    if (t >= NCB*MEMB) return;
    const float* row = emb + (size_t)t * DEMB;
    float acc = 0.f;
    #pragma unroll 8
    for (int d = 0; d < DEMB; d++) {
        float v = row[d];
        acc = __fadd_rn(acc, __fmul_rn(v, v));
    }
    g_esq[t] = acc;
}

// ---------------- x_sq (exact sequential) ----------------
__global__ void __launch_bounds__(256)
xsq_kernel(const float* __restrict__ x) {
    __shared__ float tile[8192];
    const int n = blockIdx.x & 7, b = blockIdx.x >> 3, tid = threadIdx.x;
    const size_t base = (size_t)b*65536 + (size_t)n*8192;
    for (int i = tid; i < 8192; i += 256) tile[i] = x[base + i];
    __syncthreads();
    if (tid < 64) {
        float acc = 0.f;
        #pragma unroll 8
        for (int d = 0; d < DEMB; d++) {
            float v = tile[d*64 + tid];
            acc = __fadd_rn(acc, __fmul_rn(v, v));
        }
        g_xsq[n*LPER + b*HLAT + tid] = acc;
    }
}

// ---------------- embedding -> swizzled bf16 hi/lo tiles ----------------
// chunk = 64 codes: elem = ((n*16+mc)*64 + row)*128 + ((chunk16 ^ (row&7))<<3) + (d&7)
__global__ void bprep_kernel(const float* __restrict__ emb) {
    int u = blockIdx.x * blockDim.x + threadIdx.x;
    if (u >= NCB*MEMB*DEMB) return;
    float v = emb[u];
    int d = u & 127, m = (u >> 7) & 1023, n = u >> 17;
    __nv_bfloat16 h = __float2bfloat16(v);
    __nv_bfloat16 l = __float2bfloat16(v - __bfloat162float(h));
    int row = m & 63, mc = m >> 6;
    int elem = ((n*16 + mc)*64 + row)*128 + (((d >> 3) ^ (row & 7)) << 3) + (d & 7);
    g_bhi[elem] = h;
    g_blo[elem] = l;
}

// ---------------- pass 1: tensor-core (mma.sync) approximate argmin ----------------
// CTA = (n, l-tile of 64) = one batch row b. 256 threads = 8 warps = 2(l) x 4(m).
// Warp tile 32x16. m-chunks of 64 codes, 16 iterations, B double-buffered cp.async.
// 2 CTAs/SM -> decoupled barrier chains keep the tensor pipe fed.
__global__ void __launch_bounds__(256, 2)
argmin_mma(const float* __restrict__ x) {
    extern __shared__ char smraw[];
    uint32_t sraw = smem_u32(smraw);
    uint32_t sb = (sraw + 1023u) & ~1023u;
    char* sm = smraw + (sb - sraw);
    __nv_bfloat16* Ahi = (__nv_bfloat16*)(sm);            // 16KB @0
    __nv_bfloat16* Alo = (__nv_bfloat16*)(sm + 16384);    // 16KB
    // B buffers: buf0 @32768 (hi 16KB, lo 16KB), buf1 @65536
    float* esq_s = (float*)(sm + 98304);                  // 4KB
    float* sbest = (float*)(sm + 102400);                 // 256 f32
    float* ssec  = (float*)(sm + 103424);                 // 256 f32
    int*   sidx  = (int*)  (sm + 104448);                 // 256 int

    const int n  = blockIdx.x >> 8;
    const int lt = blockIdx.x & 255;     // == batch row b
    const int l0 = lt * 64;
    const int tid  = threadIdx.x;
    const int lane = tid & 31;
    const int w    = tid >> 5;
    const int wl   = w & 1;     // l half (32 rows)
    const int wm   = w >> 1;    // m quarter (16 cols of the 64-chunk)

    // ---- prefetch B chunk 0 into buf0 (overlaps with A staging) ----
    {
        const char* srcHi = (const char*)(g_bhi + ((size_t)(n*16 + 0) << 13));
        const char* srcLo = (const char*)(g_blo + ((size_t)(n*16 + 0) << 13));
        uint32_t dstHi = sb + 32768, dstLo = sb + 32768 + 16384;
        #pragma unroll
        for (int i = 0; i < 4; i++) {
            cp16(dstHi + (tid + i*256)*16, srcHi + (tid + i*256)*16);
            cp16(dstLo + (tid + i*256)*16, srcLo + (tid + i*256)*16);
        }
        CP_COMMIT();
    }

    // stage e_sq
    for (int i = tid; i < 1024; i += 256) esq_s[i] = g_esq[n*1024 + i];

    // stage + split-convert A tile (swizzled): rows j = h (0..63), cols d
    for (int idx = tid; idx < 8192; idx += 256) {
        int d = idx >> 6, j = idx & 63;
        float v = x[(size_t)lt*65536 + (size_t)n*8192 + d*64 + j];
        __nv_bfloat16 h = __float2bfloat16(v);
        __nv_bfloat16 l = __float2bfloat16(v - __bfloat162float(h));
        int elem = j*128 + (((d >> 3) ^ (j & 7)) << 3) + (d & 7);
        Ahi[elem] = h; Alo[elem] = l;
    }

    // ldmatrix per-lane address precompute
    const uint32_t sAh = sb, sBh0 = sb + 32768;
    const int q  = lane >> 3;
    const int r8 = lane & 7;
    const int cqA = q >> 1;
    const int cqB = q & 1;
    uint32_t aBase[2]; int a7[2];
    #pragma unroll
    for (int t2 = 0; t2 < 2; t2++) {
        int rowA = wl*32 + t2*16 + r8 + (q & 1)*8;
        aBase[t2] = sAh + rowA*256; a7[t2] = rowA & 7;
    }
    uint32_t bBase; int b7;
    {
        int rowB = wm*16 + r8 + (q >> 1)*8;
        bBase = sBh0 + rowB*256; b7 = rowB & 7;
    }

    float best[4], sec[4];
    int   idxm[4];
    #pragma unroll
    for (int s = 0; s < 4; s++) { best[s] = 3.4e38f; sec[s] = 3.4e38f; idxm[s] = 0; }

    const int col2 = (lane & 3) * 2;

    for (int mc = 0; mc < 16; mc++) {
        // prefetch next chunk into the other buffer, then wait for current
        if (mc < 15) {
            const char* srcHi = (const char*)(g_bhi + ((size_t)(n*16 + mc + 1) << 13));
            const char* srcLo = (const char*)(g_blo + ((size_t)(n*16 + mc + 1) << 13));
            uint32_t dbuf = sb + 32768 + (uint32_t)(((mc + 1) & 1) * 32768);
            #pragma unroll
            for (int i = 0; i < 4; i++) {
                cp16(dbuf + (tid + i*256)*16,         srcHi + (tid + i*256)*16);
                cp16(dbuf + 16384 + (tid + i*256)*16, srcLo + (tid + i*256)*16);
            }
            CP_COMMIT();
            CP_WAIT(1);
        } else {
            CP_WAIT(0);
        }
        __syncthreads();   // current buffer visible (also covers A on mc=0)

        const uint32_t bufOff = (uint32_t)((mc & 1) * 32768);

        float acc[2][2][4];
        #pragma unroll
        for (int t2 = 0; t2 < 2; t2++)
            #pragma unroll
            for (int mt = 0; mt < 2; mt++)
                #pragma unroll
                for (int c = 0; c < 4; c++) acc[t2][mt][c] = 0.f;

        #pragma unroll
        for (int ks = 0; ks < 8; ks++) {
            const int ks2 = ks * 2;
            uint32_t ah[2][4], al[2][4];
            #pragma unroll
            for (int t2 = 0; t2 < 2; t2++) {
                uint32_t off = (uint32_t)(((ks2 + cqA) ^ a7[t2]) << 4);
                ldsm4(ah[t2], aBase[t2] + off);
                ldsm4(al[t2], aBase[t2] + off + 16384);
            }
            uint32_t bh[4], bl[4];
            {
                uint32_t off = (uint32_t)(((ks2 + cqB) ^ b7) << 4) + bufOff;
                ldsm4(bh, bBase + off);
                ldsm4(bl, bBase + off + 16384);
            }
            #pragma unroll
            for (int t2 = 0; t2 < 2; t2++) {
                mma_bf16(acc[t2][0], ah[t2], &bh[0]);
                mma_bf16(acc[t2][1], ah[t2], &bh[2]);
                mma_bf16(acc[t2][0], ah[t2], &bl[0]);
                mma_bf16(acc[t2][1], ah[t2], &bl[2]);
                mma_bf16(acc[t2][0], al[t2], &bh[0]);
                mma_bf16(acc[t2][1], al[t2], &bh[2]);
            }
        }

        // epilogue: t = e_sq - 2*dot ; update best/second
        const int mbase = mc*64 + wm*16;
        #pragma unroll
        for (int t2 = 0; t2 < 2; t2++) {
            #pragma unroll
            for (int mt = 0; mt < 2; mt++) {
                float e0 = esq_s[mbase + mt*8 + col2];
                float e1 = esq_s[mbase + mt*8 + col2 + 1];
                int m0 = mbase + mt*8 + col2;
                {
                    int s = t2*2;
                    float ta = e0 - 2.f*acc[t2][mt][0];
                    float tb = e1 - 2.f*acc[t2][mt][1];
                    if (ta < best[s]) { sec[s] = best[s]; best[s] = ta; idxm[s] = m0; }
                    else if (ta < sec[s]) sec[s] = ta;
                    if (tb < best[s]) { sec[s] = best[s]; best[s] = tb; idxm[s] = m0 + 1; }
                    else if (tb < sec[s]) sec[s] = tb;
                }
                {
                    int s = t2*2 + 1;
                    float ta = e0 - 2.f*acc[t2][mt][2];
                    float tb = e1 - 2.f*acc[t2][mt][3];
                    if (ta < best[s]) { sec[s] = best[s]; best[s] = ta; idxm[s] = m0; }
                    else if (ta < sec[s]) sec[s] = ta;
                    if (tb < best[s]) { sec[s] = best[s]; best[s] = tb; idxm[s] = m0 + 1; }
                    else if (tb < sec[s]) sec[s] = tb;
                }
            }
        }
        __syncthreads();   // all warps done reading this buffer before overwrite
    }

    // quad reduce (lanes sharing lane>>2 hold the same rows)
    #pragma unroll
    for (int s = 0; s < 4; s++) {
        float b = best[s], sc = sec[s];
        int   im = idxm[s];
        #pragma unroll
        for (int off = 1; off <= 2; off <<= 1) {
            float ob = __shfl_xor_sync(0xffffffffu, b,  off);
            float os = __shfl_xor_sync(0xffffffffu, sc, off);
            int   oi = __shfl_xor_sync(0xffffffffu, im, off);
            if (ob < b || (ob == b && oi < im)) {
                sc = fminf(b, os); b = ob; im = oi;
            } else {
                sc = fminf(sc, ob);
            }
        }
        best[s] = b; sec[s] = sc; idxm[s] = im;
    }
    if ((lane & 3) == 0) {
        const int g = lane >> 2;
        #pragma unroll
        for (int s = 0; s < 4; s++) {
            int row = wl*32 + (s >> 1)*16 + g + (s & 1)*8;
            sbest[wm*64 + row] = best[s];
            ssec [wm*64 + row] = sec[s];
            sidx [wm*64 + row] = idxm[s];
        }
    }
    __syncthreads();

    if (tid < 64) {
        float b = sbest[tid], s = ssec[tid];
        int   im = sidx[tid];
        #pragma unroll
        for (int qq = 1; qq < 4; qq++) {
            float bq = sbest[qq*64 + tid];
            float sq = ssec [qq*64 + tid];
            int   iq = sidx [qq*64 + tid];
            if (bq < b || (bq == b && iq < im)) { s = fminf(b, sq); b = bq; im = iq; }
            else { s = fminf(s, bq); }
        }
        int l = l0 + tid;
        g_indices[n*LPER + l] = im;
        if (s - b < MARGIN) {
            int p = atomicAdd(&g_ucount, 1);
            g_ulist[p] = (n << 14) | l;
        }
    }
}

// ---------------- pass 2: exact rescan of uncertain rows ----------------
__global__ void __launch_bounds__(256)
fixup_kernel(const float* __restrict__ x, const float* __restrict__ emb) {
    __shared__ float xs[128];
    __shared__ float sD[256];
    __shared__ int   sM[256];
    const int tid = threadIdx.x;
    const int cnt = g_ucount;
    for (int u = blockIdx.x; u < cnt; u += gridDim.x) {
        int id = g_ulist[u];
        int n = id >> 14, l = id & 16383;
        int b = l >> 6, h = l & 63;
        __syncthreads();
        if (tid < 128) xs[tid] = x[(size_t)b*65536 + (size_t)n*8192 + tid*64 + h];
        __syncthreads();
        float xsq = g_xsq[n*LPER + l];
        float bD = 3.4e38f; int bM = 0;
        for (int mm = 0; mm < 4; mm++) {
            int m = mm*256 + tid;
            const float4* er = (const float4*)(emb + ((size_t)n*1024 + m)*128);
            float c = 0.f;
            #pragma unroll 8
            for (int qq = 0; qq < 32; qq++) {   // ascending-d sequential fmaf chain
                float4 e4 = er[qq];
                c = fmaf(xs[qq*4+0], e4.x, c);
                c = fmaf(xs[qq*4+1], e4.y, c);
                c = fmaf(xs[qq*4+2], e4.z, c);
                c = fmaf(xs[qq*4+3], e4.w, c);
            }
            float D = __fsub_rn(__fadd_rn(g_esq[n*1024 + m], xsq), 2.f*c);
            if (D < bD || (D == bD && m < bM)) { bD = D; bM = m; }
        }
        sD[tid] = bD; sM[tid] = bM;
        __syncthreads();
        for (int st = 128; st; st >>= 1) {
            if (tid < st) {
                float oD = sD[tid+st]; int oM = sM[tid+st];
                if (oD < sD[tid] || (oD == sD[tid] && oM < sM[tid])) { sD[tid] = oD; sM[tid] = oM; }
            }
            __syncthreads();
        }
        if (tid == 0) g_indices[n*LPER + l] = sM[0];
    }
}

// ---------------- gather + z_q + loss partials + indices out ----------------
__global__ void __launch_bounds__(256)
gather_kernel(const float* __restrict__ x, const float* __restrict__ emb,
              float* __restrict__ out, float* __restrict__ out_idx, int write_extras) {
    __shared__ int   midx[64];
    __shared__ float rows[64*129];
    __shared__ float red[256];
    const int n = blockIdx.x & 7, b = blockIdx.x >> 3, tid = threadIdx.x;

    if (tid < 64) {
        int m = g_indices[n*LPER + b*HLAT + tid];
        midx[tid] = m;
        if (write_extras) out_idx[b*(NCB*HLAT) + n*HLAT + tid] = (float)m;
    }
    __syncthreads();
    for (int idx = tid; idx < 64*128; idx += 256) {
        int r = idx >> 7, d = idx & 127;
        rows[r*129 + d] = emb[(size_t)n*(MEMB*DEMB) + (size_t)midx[r]*DEMB + d];
    }
    __syncthreads();
    float s = 0.f;
    const size_t base = (size_t)b*65536 + (size_t)n*8192;
    for (int idx = tid; idx < 8192; idx += 256) {
        int d = idx >> 6, h = idx & 63;
        float q  = rows[h*129 + d];
        float xv = x[base + idx];
        out[base + idx] = q;
        float df = xv - q;
        s += df*df;
    }
    red[tid] = s;
    __syncthreads();
    for (int st = 128; st; st >>= 1) { if (tid < st) red[tid] += red[tid+st]; __syncthreads(); }
    if (tid == 0) g_part[blockIdx.x] = red[0];
}

// ---------------- entropy ----------------
__global__ void entropy_kernel() {
    __shared__ int   hist[MEMB];
    __shared__ float red[256];
    const int n = blockIdx.x, tid = threadIdx.x;
    for (int i = tid; i < MEMB; i += 256) hist[i] = 0;
    __syncthreads();
    for (int l = tid; l < LPER; l += 256) atomicAdd(&hist[g_indices[n*LPER + l]], 1);
    __syncthreads();
    float s = 0.f;
    for (int m = tid; m < MEMB; m += 256) {
        float p = (float)hist[m] * (1.f / (float)LPER);
        s += p * logf(p + 1e-10f);
    }
    red[tid] = s;
    __syncthreads();
    for (int st = 128; st; st >>= 1) { if (tid < st) red[tid] += red[tid+st]; __syncthreads(); }
    if (tid == 0) g_ent[n] = -red[0];
}

// ---------------- finalize ----------------
__global__ void finalize_kernel(float* __restrict__ out, int write_scalars) {
    __shared__ float red[256];
    const int tid = threadIdx.x;
    float s = 0.f;
    for (int i = tid; i < 2048; i += 256) s += g_part[i];
    red[tid] = s;
    __syncthreads();
    for (int st = 128; st; st >>= 1) { if (tid < st) red[tid] += red[tid+st]; __syncthreads(); }
    if (tid == 0 && write_scalars) {
        float loss = 0.25f * red[0] / (float)ZQ_ELEMS;
        float ent = 0.f, perp = 0.f;
        #pragma unroll
        for (int n = 0; n < NCB; n++) { ent += g_ent[n]; perp += expf(g_ent[n]); }
        out[ZQ_ELEMS + 0] = loss;
        out[ZQ_ELEMS + 1] = ent * (1.f / NCB);
        out[ZQ_ELEMS + 2] = perp * (1.f / NCB);
    }
}

// ---------------- launch ----------------
extern "C" void kernel_launch(void* const* d_in, const int* in_sizes, int n_in,
                              void* d_out, int out_size) {
    const float* x   = (const float*)d_in[0];
    const float* emb = (const float*)d_in[1];
    if (n_in >= 2 && in_sizes[0] == NCB*MEMB*DEMB && in_sizes[1] == ZQ_ELEMS) {
        const float* t = x; x = emb; emb = t;
    }
    float* out = (float*)d_out;
    const int full = (out_size >= ZQ_ELEMS + 3 + IDX_ELEMS) ? 1 : 0;

    const int SMEM_ARG = 105472 + 1024;
    cudaFuncSetAttribute(argmin_mma, cudaFuncAttributeMaxDynamicSharedMemorySize, SMEM_ARG);

    esq_kernel<<<(NCB*MEMB + 255)/256, 256>>>(emb);
    xsq_kernel<<<BATCH*NCB, 256>>>(x);
    bprep_kernel<<<(NCB*MEMB*DEMB + 255)/256, 256>>>(emb);
    argmin_mma<<<NCB * (LPER/64), 256, SMEM_ARG>>>(x);
    fixup_kernel<<<512, 256>>>(x, emb);
    gather_kernel<<<BATCH*NCB, 256>>>(x, emb, out, out + ZQ_ELEMS + 3, full);
    entropy_kernel<<<NCB, 256>>>();
    finalize_kernel<<<1, 256>>>(out, full);
}